// round 4
// baseline (speedup 1.0000x reference)
#include <cuda_runtime.h>
#include <cuda_bf16.h>

namespace {

constexpr int NQ     = 12;
constexpr int DIM    = 4096;
constexpr int LAYERS = 8;
constexpr int FEAT   = 3072;
constexpr int NCLASS = 10;
constexpr int TPB    = 128;   // threads per CTA
constexpr int AMPS   = 32;    // amplitudes per thread (per state)
constexpr int RS     = 33;    // smem row stride in float2 units (conflict-free)

using u64 = unsigned long long;

// ---- packed f32x2 helpers (sm_100+ PTX; SASS FFMA2/FMUL2) ----
__device__ __forceinline__ u64 pack2(float lo, float hi) {
    u64 r; asm("mov.b64 %0, {%1, %2};" : "=l"(r) : "f"(lo), "f"(hi)); return r;
}
__device__ __forceinline__ void unpack2(u64 v, float& lo, float& hi) {
    asm("mov.b64 {%0, %1}, %2;" : "=f"(lo), "=f"(hi) : "l"(v));
}
__device__ __forceinline__ u64 mul2(u64 a, u64 b) {
    u64 r; asm("mul.rn.f32x2 %0, %1, %2;" : "=l"(r) : "l"(a), "l"(b)); return r;
}
__device__ __forceinline__ u64 add2(u64 a, u64 b) {
    u64 r; asm("add.rn.f32x2 %0, %1, %2;" : "=l"(r) : "l"(a), "l"(b)); return r;
}
__device__ __forceinline__ u64 fma2(u64 a, u64 b, u64 c) {
    u64 r; asm("fma.rn.f32x2 %0, %1, %2, %3;" : "=l"(r) : "l"(a), "l"(b), "l"(c)); return r;
}

// Each CTA simulates TWO batch rows (2*bb, 2*bb+1) packed lane-wise in f32x2.
// Arrangement A: amplitude i = (t<<5) | r   (bits 0-4 register-local)
// Arrangement B: amplitude i = (r<<7) | t   (bits 7-11 register-local)
// Qubit q acts on bit p = 11 - q. CNOT chain == Gray map j = i ^ (i>>1).

__global__ void __launch_bounds__(TPB, 4) qnn_kernel(
    const float* __restrict__ x,       // [B, 3072]
    const float* __restrict__ angles,  // [8, 12]
    const float* __restrict__ W,       // [10, 4096]
    const float* __restrict__ bias,    // [10]
    float* __restrict__ out)           // [B, 10]
{
    __shared__ float s_c[LAYERS][NQ];
    __shared__ float s_s[LAYERS][NQ];
    __shared__ u64   buf[128 * RS];    // 33792 B packed exchange buffer
    __shared__ u64   sred[4 * NCLASS]; // packed reductions

    const int t    = threadIdx.x;
    const int lane = t & 31;
    const int warp = t >> 5;
    const int bb   = blockIdx.x;

    // Trig table: qubit q -> bit position p = 11 - q.
    if (t < LAYERS * NQ) {
        const int l = t / NQ;
        const int q = t - l * NQ;
        const float a = angles[t];
        const int p = NQ - 1 - q;
        s_c[l][p] = cosf(a);
        s_s[l][p] = sinf(a);
    }

    // Load two input rows, pack (row0, row1) per amplitude. Pad 3072->4096.
    u64 v[AMPS];
    if (t < FEAT / AMPS) {   // t < 96
        const float4* x0 = reinterpret_cast<const float4*>(x)
                         + (size_t)(2 * bb)     * (FEAT / 4) + t * (AMPS / 4);
        const float4* x1 = reinterpret_cast<const float4*>(x)
                         + (size_t)(2 * bb + 1) * (FEAT / 4) + t * (AMPS / 4);
        #pragma unroll
        for (int i = 0; i < AMPS / 4; i++) {
            const float4 a4 = x0[i];
            const float4 b4 = x1[i];
            v[4*i+0] = pack2(a4.x, b4.x);
            v[4*i+1] = pack2(a4.y, b4.y);
            v[4*i+2] = pack2(a4.z, b4.z);
            v[4*i+3] = pack2(a4.w, b4.w);
        }
    } else {
        #pragma unroll
        for (int r = 0; r < AMPS; r++) v[r] = 0ull;
    }

    // Per-state L2 normalization (packed sum of squares).
    u64 ssq = 0ull;
    #pragma unroll
    for (int r = 0; r < AMPS; r++) ssq = fma2(v[r], v[r], ssq);
    #pragma unroll
    for (int o = 16; o > 0; o >>= 1)
        ssq = add2(ssq, __shfl_xor_sync(0xffffffffu, ssq, o));
    if (lane == 0) sred[warp] = ssq;
    __syncthreads();   // also publishes trig table
    {
        const u64 s4 = add2(add2(sred[0], sred[1]), add2(sred[2], sred[3]));
        float n0, n1; unpack2(s4, n0, n1);
        const u64 rn2 = pack2(rsqrtf(n0), rsqrtf(n1));
        #pragma unroll
        for (int r = 0; r < AMPS; r++) v[r] = mul2(v[r], rn2);
    }

    const int g_t   = t ^ (t >> 1);           // 7-bit Gray of thread id
    const int baseA = t * RS;
    const int baseB = warp * RS + lane;

    #pragma unroll 1
    for (int l = 0; l < LAYERS; l++) {
        __syncthreads();   // WAR: previous layer's reads of buf complete

        // ---- gates on bits 0..4 (register butterflies, packed) ----
        #pragma unroll
        for (int p = 0; p < 5; p++) {
            const float c = s_c[l][p], s = s_s[l][p];
            const u64 c2 = pack2(c, c), s2 = pack2(s, s), ns2 = pack2(-s, -s);
            const int m = 1 << p;
            #pragma unroll
            for (int lo = 0; lo < AMPS; lo += 2 * m)
                #pragma unroll
                for (int k = 0; k < m; k++) {
                    const int r0 = lo + k, r1 = r0 + m;
                    const u64 a0 = v[r0], a1 = v[r1];
                    v[r0] = fma2(ns2, a1, mul2(c2, a0));
                    v[r1] = fma2(s2,  a0, mul2(c2, a1));
                }
        }

        // ---- gates on bits 5,6 via shfl_xor (lane bits 0,1) ----
        #pragma unroll
        for (int p = 5; p < 7; p++) {
            const float c = s_c[l][p], s = s_s[l][p];
            const int mask = 1 << (p - 5);
            const float se = (lane & mask) ? s : -s;
            const u64 c2 = pack2(c, c), se2 = pack2(se, se);
            #pragma unroll
            for (int r = 0; r < AMPS; r++) {
                const u64 pr = __shfl_xor_sync(0xffffffffu, v[r], mask);
                v[r] = fma2(se2, pr, mul2(c2, v[r]));
            }
        }

        // ---- transpose A -> B ----
        #pragma unroll
        for (int r = 0; r < AMPS; r++) buf[baseA + r] = v[r];
        __syncthreads();
        #pragma unroll
        for (int rp = 0; rp < AMPS; rp++) v[rp] = buf[baseB + rp * 4 * RS];

        // ---- gates on bits 7..11 (register butterflies in B) ----
        #pragma unroll
        for (int p = 0; p < 5; p++) {
            const float c = s_c[l][p + 7], s = s_s[l][p + 7];
            const u64 c2 = pack2(c, c), s2 = pack2(s, s), ns2 = pack2(-s, -s);
            const int m = 1 << p;
            #pragma unroll
            for (int lo = 0; lo < AMPS; lo += 2 * m)
                #pragma unroll
                for (int k = 0; k < m; k++) {
                    const int r0 = lo + k, r1 = r0 + m;
                    const u64 a0 = v[r0], a1 = v[r1];
                    v[r0] = fma2(ns2, a1, mul2(c2, a0));
                    v[r1] = fma2(s2,  a0, mul2(c2, a1));
                }
        }

        __syncthreads();   // WAR: transpose reads complete before scatter writes

        // ---- Gray scatter B -> A: j = i ^ (i>>1), i = (rp<<7)|t ----
        #pragma unroll
        for (int rp = 0; rp < AMPS; rp++) {
            const int K = (rp << 7) ^ (rp << 6);
            const int j = K ^ g_t;
            buf[(j >> 5) * RS + (j & 31)] = v[rp];
        }
        __syncthreads();
        #pragma unroll
        for (int r = 0; r < AMPS; r++) v[r] = buf[baseA + r];
    }

    // ---- probabilities (packed square) ----
    #pragma unroll
    for (int r = 0; r < AMPS; r++) v[r] = mul2(v[r], v[r]);

    // ---- readout: out[k] = sum_i probs[i] * W[k,i] + b[k], both states ----
    #pragma unroll 1
    for (int k = 0; k < NCLASS; k++) {
        const float4* w4 = reinterpret_cast<const float4*>(W + (size_t)k * DIM)
                         + t * (AMPS / 4);
        u64 acc = 0ull;
        #pragma unroll
        for (int i = 0; i < AMPS / 4; i++) {
            const float4 w = w4[i];
            acc = fma2(v[4*i+0], pack2(w.x, w.x), acc);
            acc = fma2(v[4*i+1], pack2(w.y, w.y), acc);
            acc = fma2(v[4*i+2], pack2(w.z, w.z), acc);
            acc = fma2(v[4*i+3], pack2(w.w, w.w), acc);
        }
        #pragma unroll
        for (int o = 16; o > 0; o >>= 1)
            acc = add2(acc, __shfl_xor_sync(0xffffffffu, acc, o));
        if (lane == 0) sred[k * 4 + warp] = acc;
    }
    __syncthreads();
    if (t < NCLASS) {
        const u64 s4 = add2(add2(sred[t*4+0], sred[t*4+1]),
                            add2(sred[t*4+2], sred[t*4+3]));
        float a0, a1; unpack2(s4, a0, a1);
        const float bk = bias[t];
        out[(size_t)(2 * bb)     * NCLASS + t] = a0 + bk;
        out[(size_t)(2 * bb + 1) * NCLASS + t] = a1 + bk;
    }
}

} // namespace

extern "C" void kernel_launch(void* const* d_in, const int* in_sizes, int n_in,
                              void* d_out, int out_size) {
    const float* x      = (const float*)d_in[0];
    const float* angles = (const float*)d_in[1];
    const float* W      = (const float*)d_in[2];
    const float* bias   = (const float*)d_in[3];
    const int batch = in_sizes[0] / FEAT;   // 2048
    qnn_kernel<<<batch / 2, TPB>>>(x, angles, W, bias, (float*)d_out);
}

// round 5
// speedup vs baseline: 1.4990x; 1.4990x over previous
#include <cuda_runtime.h>
#include <cuda_bf16.h>

namespace {

constexpr int NQ     = 12;
constexpr int DIM    = 4096;
constexpr int LAYERS = 8;
constexpr int FEAT   = 3072;
constexpr int NCLASS = 10;
constexpr int TPB    = 256;   // threads per CTA, one state per CTA
constexpr int AMPS   = 16;    // amplitudes per thread
constexpr int RS     = 17;    // smem row stride (floats): 16 cols + 1 pad

// Arrangement A: amplitude i = (t<<4) | r
//   bits 0-3 = r (register), bits 4-8 = lane (shfl), bits 9-11 = warp
// Arrangement B: amplitude i = (rp<<8) | t
//   bits 8-11 = rp (register), bits 0-7 = t
// Qubit q acts on bit p = 11 - q.  The per-layer CNOT chain is the Gray
// map j = i ^ (i >> 1).  All cos factors are folded into one global scalar
// applied at normalization (tan-form butterflies: 2 FFMA each).

__global__ void __launch_bounds__(TPB, 5) qnn_kernel(
    const float* __restrict__ x,       // [B, 3072]
    const float* __restrict__ angles,  // [8, 12]
    const float* __restrict__ W,       // [10, 4096]
    const float* __restrict__ bias,    // [10]
    float* __restrict__ out)           // [B, 10]
{
    __shared__ float s_t[LAYERS][NQ];      // tan table, [layer][bit pos]
    __shared__ float bufA[TPB * RS];       // transpose buffer (17408 B)
    __shared__ float bufB[TPB * RS];       // gray-scatter buffer
    __shared__ float s_prod[8];            // per-warp cos products
    __shared__ float s_norm[8];            // per-warp sum-of-squares
    __shared__ float sred[8 * NCLASS];     // epilogue partials

    const int t    = threadIdx.x;
    const int lane = t & 31;
    const int warp = t >> 5;
    const int bb   = blockIdx.x;

    // ---- trig: tan per gate; cos accumulated into a global product ----
    float cp = 1.0f;
    if (t < LAYERS * NQ) {
        const int l = t / NQ;
        const int q = t - l * NQ;
        const float a = angles[t];
        const int p = NQ - 1 - q;       // qubit q -> bit position p
        const float c = cosf(a);
        s_t[l][p] = sinf(a) / c;
        cp = c;
    }
    #pragma unroll
    for (int o = 16; o > 0; o >>= 1)
        cp *= __shfl_xor_sync(0xffffffffu, cp, o);
    if (lane == 0) s_prod[warp] = cp;

    // ---- load input row (pad 3072 -> 4096), arrangement A ----
    float v[AMPS];
    if (t < FEAT / AMPS) {   // t < 192
        const float4* x4 = reinterpret_cast<const float4*>(x)
                         + (size_t)bb * (FEAT / 4) + t * (AMPS / 4);
        #pragma unroll
        for (int i = 0; i < AMPS / 4; i++) {
            const float4 w4 = x4[i];
            v[4*i+0] = w4.x; v[4*i+1] = w4.y; v[4*i+2] = w4.z; v[4*i+3] = w4.w;
        }
    } else {
        #pragma unroll
        for (int r = 0; r < AMPS; r++) v[r] = 0.0f;
    }

    // ---- L2 norm (and fold in the global cos product) ----
    float ssq = 0.0f;
    #pragma unroll
    for (int r = 0; r < AMPS; r++) ssq = fmaf(v[r], v[r], ssq);
    #pragma unroll
    for (int o = 16; o > 0; o >>= 1) ssq += __shfl_xor_sync(0xffffffffu, ssq, o);
    if (lane == 0) s_norm[warp] = ssq;
    __syncthreads();   // publishes trig table, s_prod, s_norm
    {
        float tot = 0.0f, ctot = 1.0f;
        #pragma unroll
        for (int w = 0; w < 8; w++) { tot += s_norm[w]; ctot *= s_prod[w]; }
        const float rn = rsqrtf(tot) * ctot;
        #pragma unroll
        for (int r = 0; r < AMPS; r++) v[r] *= rn;
    }

    const int g_t   = t ^ (t >> 1);      // 8-bit Gray of thread id
    const int baseA = t * RS;
    const int baseB = ((t >> 4) * RS) + (t & 15);   // + (rp<<4)*RS per rp

    #pragma unroll 1
    for (int l = 0; l < LAYERS; l++) {
        // ---- gates on bits 0..3 (register butterflies, tan form) ----
        #pragma unroll
        for (int p = 0; p < 4; p++) {
            const float tg = s_t[l][p];
            const int m = 1 << p;
            #pragma unroll
            for (int lo = 0; lo < AMPS; lo += 2 * m)
                #pragma unroll
                for (int k = 0; k < m; k++) {
                    const int r0 = lo + k, r1 = r0 + m;
                    const float a0 = v[r0], a1 = v[r1];
                    v[r0] = fmaf(-tg, a1, a0);
                    v[r1] = fmaf( tg, a0, a1);
                }
        }

        // ---- gates on bits 4..7 via shfl_xor (lane bits 0..3) ----
        #pragma unroll
        for (int p = 4; p < 8; p++) {
            const float tg = s_t[l][p];
            const int mask = 1 << (p - 4);
            const float se = (lane & mask) ? tg : -tg;
            #pragma unroll
            for (int r = 0; r < AMPS; r++) {
                const float pr = __shfl_xor_sync(0xffffffffu, v[r], mask);
                v[r] = fmaf(se, pr, v[r]);
            }
        }

        // ---- transpose A -> B through bufA ----
        #pragma unroll
        for (int r = 0; r < AMPS; r++) bufA[baseA + r] = v[r];
        __syncthreads();
        #pragma unroll
        for (int rp = 0; rp < AMPS; rp++) v[rp] = bufA[baseB + (rp << 4) * RS];

        // ---- gates on bits 8..11 (register butterflies in B) ----
        #pragma unroll
        for (int p = 0; p < 4; p++) {
            const float tg = s_t[l][p + 8];
            const int m = 1 << p;
            #pragma unroll
            for (int lo = 0; lo < AMPS; lo += 2 * m)
                #pragma unroll
                for (int k = 0; k < m; k++) {
                    const int r0 = lo + k, r1 = r0 + m;
                    const float a0 = v[r0], a1 = v[r1];
                    v[r0] = fmaf(-tg, a1, a0);
                    v[r1] = fmaf( tg, a0, a1);
                }
        }

        // ---- Gray scatter B -> A through bufB: j = i ^ (i>>1) ----
        #pragma unroll
        for (int rp = 0; rp < AMPS; rp++) {
            const int j = ((rp << 8) ^ (rp << 7)) ^ g_t;
            bufB[(j >> 4) * RS + (j & 15)] = v[rp];
        }
        __syncthreads();
        #pragma unroll
        for (int r = 0; r < AMPS; r++) v[r] = bufB[baseA + r];
    }

    // ---- probabilities ----
    #pragma unroll
    for (int r = 0; r < AMPS; r++) v[r] = v[r] * v[r];

    // ---- readout: out[k] = sum_i probs[i] * W[k,i] + b[k] ----
    #pragma unroll 1
    for (int k = 0; k < NCLASS; k++) {
        const float4* w4 = reinterpret_cast<const float4*>(W + (size_t)k * DIM)
                         + t * (AMPS / 4);
        float a = 0.0f;
        #pragma unroll
        for (int i = 0; i < AMPS / 4; i++) {
            const float4 w = w4[i];
            a = fmaf(v[4*i+0], w.x, a);
            a = fmaf(v[4*i+1], w.y, a);
            a = fmaf(v[4*i+2], w.z, a);
            a = fmaf(v[4*i+3], w.w, a);
        }
        #pragma unroll
        for (int o = 16; o > 0; o >>= 1) a += __shfl_xor_sync(0xffffffffu, a, o);
        if (lane == 0) sred[k * 8 + warp] = a;
    }
    __syncthreads();
    if (t < NCLASS) {
        float a = bias[t];
        #pragma unroll
        for (int w = 0; w < 8; w++) a += sred[t * 8 + w];
        out[bb * NCLASS + t] = a;
    }
}

} // namespace

extern "C" void kernel_launch(void* const* d_in, const int* in_sizes, int n_in,
                              void* d_out, int out_size) {
    const float* x      = (const float*)d_in[0];
    const float* angles = (const float*)d_in[1];
    const float* W      = (const float*)d_in[2];
    const float* bias   = (const float*)d_in[3];
    const int batch = in_sizes[0] / FEAT;   // 2048
    qnn_kernel<<<batch, TPB>>>(x, angles, W, bias, (float*)d_out);
}